// round 14
// baseline (speedup 1.0000x reference)
#include <cuda_runtime.h>
#include <cuda_fp16.h>
#include <math.h>
#include <stdint.h>

#define Bb 4
#define Ss 2048
#define Hh 1024
#define NH 16
#define HD 64
#define Ee 256
#define Mm (Bb*Ss)
#define LOG2E 1.44269504f

// ---------------- static device scratch -------------------------------------
__device__ __half g_qh[(size_t)Mm*Hh];   // fp16 Q (pre-scaled by 0.125*log2e)
__device__ __half g_kh[(size_t)Mm*Hh];
__device__ __half g_vh[(size_t)Mm*Hh];
__device__ __half g_eqh[(size_t)Mm*Ee];
__device__ __half g_ekh[(size_t)Mm*Ee];
__device__ __half g_biash[(size_t)Bb*Ss*Ss];  // bias pre-scaled by log2e
__device__ __half g_ctxh[(size_t)Mm*Hh];
__device__ __half g_xh[(size_t)Mm*Hh];
__device__ __half g_whr[(size_t)4*Hh*Hh + 2*Hh*Ee];

#define OFF_WQ  ((size_t)0)
#define OFF_WK  ((size_t)1*Hh*Hh)
#define OFF_WV  ((size_t)2*Hh*Hh)
#define OFF_WO  ((size_t)3*Hh*Hh)
#define OFF_WEQ ((size_t)4*Hh*Hh)
#define OFF_WEK ((size_t)4*Hh*Hh + (size_t)Hh*Ee)

// ---------------- helpers ----------------------------------------------------
__device__ __forceinline__ void mma16h(float& c0, float& c1, float& c2, float& c3,
                                       unsigned a0, unsigned a1, unsigned a2, unsigned a3,
                                       unsigned b0, unsigned b1) {
    asm volatile("mma.sync.aligned.m16n8k16.row.col.f32.f16.f16.f32 "
                 "{%0,%1,%2,%3},{%4,%5,%6,%7},{%8,%9},{%0,%1,%2,%3};"
                 : "+f"(c0), "+f"(c1), "+f"(c2), "+f"(c3)
                 : "r"(a0), "r"(a1), "r"(a2), "r"(a3), "r"(b0), "r"(b1));
}
__device__ __forceinline__ void mma16hh(unsigned& c0, unsigned& c1,
                                        unsigned a0, unsigned a1, unsigned a2, unsigned a3,
                                        unsigned b0, unsigned b1) {
    asm volatile("mma.sync.aligned.m16n8k16.row.col.f16.f16.f16.f16 "
                 "{%0,%1},{%2,%3,%4,%5},{%6,%7},{%0,%1};"
                 : "+r"(c0), "+r"(c1)
                 : "r"(a0), "r"(a1), "r"(a2), "r"(a3), "r"(b0), "r"(b1));
}
__device__ __forceinline__ void cp16(uint32_t dst, const void* src) {
    asm volatile("cp.async.ca.shared.global [%0], [%1], 16;" :: "r"(dst), "l"(src));
}
__device__ __forceinline__ void ldsm4(unsigned& r0, unsigned& r1, unsigned& r2, unsigned& r3, uint32_t a) {
    asm volatile("ldmatrix.sync.aligned.m8n8.x4.shared.b16 {%0,%1,%2,%3}, [%4];"
                 : "=r"(r0), "=r"(r1), "=r"(r2), "=r"(r3) : "r"(a));
}
__device__ __forceinline__ void ldsm4t(unsigned& r0, unsigned& r1, unsigned& r2, unsigned& r3, uint32_t a) {
    asm volatile("ldmatrix.sync.aligned.m8n8.x4.trans.shared.b16 {%0,%1,%2,%3}, [%4];"
                 : "=r"(r0), "=r"(r1), "=r"(r2), "=r"(r3) : "r"(a));
}
__device__ __forceinline__ unsigned h2ex2(unsigned x) {
    unsigned d; asm("ex2.approx.f16x2 %0, %1;" : "=r"(d) : "r"(x)); return d;
}
#define CP_COMMIT asm volatile("cp.async.commit_group;")
#define CP_WAIT2  asm volatile("cp.async.wait_group 2;")
#define CP_WAIT1  asm volatile("cp.async.wait_group 1;")
#define CP_WAIT0  asm volatile("cp.async.wait_group 0;")

// ---------------- fp32 -> fp16 conversion passes -------------------------------
__global__ __launch_bounds__(256) void round_h(const float* __restrict__ in,
                                               __half* __restrict__ out, int n4)
{
    int i = blockIdx.x * 256 + threadIdx.x;
    if (i < n4) {
        float4 v = ((const float4*)in)[i];
        __half2* o = (__half2*)out + 2 * (size_t)i;
        o[0] = __floats2half2_rn(v.x, v.y);
        o[1] = __floats2half2_rn(v.z, v.w);
    }
}

__global__ __launch_bounds__(256) void round_w(
    const float* __restrict__ w0, const float* __restrict__ w1,
    const float* __restrict__ w2, const float* __restrict__ w3,
    const float* __restrict__ w4, const float* __restrict__ w5,
    __half* __restrict__ out)
{
    const int z = blockIdx.y;
    const float* src;
    size_t off; int n4;
    switch (z) {
        case 0: src = w0; off = OFF_WQ;  n4 = Hh * Hh / 4; break;
        case 1: src = w1; off = OFF_WK;  n4 = Hh * Hh / 4; break;
        case 2: src = w2; off = OFF_WV;  n4 = Hh * Hh / 4; break;
        case 3: src = w3; off = OFF_WO;  n4 = Hh * Hh / 4; break;
        case 4: src = w4; off = OFF_WEQ; n4 = Hh * Ee / 4; break;
        default: src = w5; off = OFF_WEK; n4 = Hh * Ee / 4; break;
    }
    int i = blockIdx.x * 256 + threadIdx.x;
    if (i < n4) {
        float4 v = ((const float4*)src)[i];
        __half2* o = (__half2*)(out + off) + 2 * (size_t)i;
        o[0] = __floats2half2_rn(v.x, v.y);
        o[1] = __floats2half2_rn(v.z, v.w);
    }
}

// =============================================================================
// fp16 GEMM core: C = A[M,K]h @ W[K,N]h + bias[N]f   (4-stage cp.async)
// MMAs use fp16 accumulators (K=32 chunks) flushed into fp32 master acc.
// =============================================================================
#define AS2 40
#define BS2 136
#define A_T2 (128*AS2)
#define B_T2 (32*BS2)
#define G2_STAGE ((A_T2 + B_T2)*2)
#define GEMMH_SMEM (4*G2_STAGE)

__device__ __forceinline__ void g_load(uint32_t sbase, const __half* A, const __half* W,
                                       int N, int K, int m0, int n0, int s, int tid)
{
    const uint32_t st = sbase + (uint32_t)((s & 3) * G2_STAGE);
    const int kt = s * 32;
    #pragma unroll
    for (int i = 0; i < 2; i++) {
        int lin = tid + i * 256, row = lin >> 2, ch = (lin & 3) * 8;
        cp16(st + (uint32_t)(row * AS2 + ch) * 2, A + (size_t)(m0 + row) * K + kt + ch);
    }
    #pragma unroll
    for (int i = 0; i < 2; i++) {
        int lin = tid + i * 256, row = lin >> 4, ch = (lin & 15) * 8;
        cp16(st + (uint32_t)(A_T2 + row * BS2 + ch) * 2, W + (size_t)(kt + row) * N + n0 + ch);
    }
}

// hAcc=1: fp16 accumulate + per-iter flush (projections). hAcc=0: fp32 acc (out-proj).
template<int hAcc>
__device__ __forceinline__ void gemmh_body(
    const __half* __restrict__ A, const __half* __restrict__ W,
    const float* __restrict__ bias, float* __restrict__ Cf, __half* __restrict__ Ch,
    int N, int K, int mode, float oscale, int m0, int n0, char* smc)
{
    const int tid = threadIdx.x, lane = tid & 31, wid = tid >> 5;
    const int wm = wid >> 2, wn = wid & 3;
    const int r = lane >> 2, c = lane & 3;
    const uint32_t sbase = (uint32_t)__cvta_generic_to_shared(smc);

    float acc[4][4][4];
    #pragma unroll
    for (int i = 0; i < 4; i++)
        #pragma unroll
        for (int j = 0; j < 4; j++)
            #pragma unroll
            for (int q = 0; q < 4; q++) acc[i][j][q] = 0.f;

    const uint32_t aLane = (uint32_t)((lane & 15) * (AS2 * 2) + (lane >> 4) * 16);
    const uint32_t bLane = (uint32_t)((lane & 15) * (BS2 * 2) + (lane >> 4) * 16);

    const int niter = K / 32;
    #pragma unroll
    for (int s = 0; s < 3; s++) { g_load(sbase, A, W, N, K, m0, n0, s, tid); CP_COMMIT; }

    for (int it = 0; it < niter; it++) {
        if (it + 2 < niter) { CP_WAIT2; }
        else if (it + 1 < niter) { CP_WAIT1; }
        else { CP_WAIT0; }
        __syncthreads();

        if (it + 3 < niter) { g_load(sbase, A, W, N, K, m0, n0, it + 3, tid); CP_COMMIT; }

        const uint32_t stA = sbase + (uint32_t)((it & 3) * G2_STAGE);
        const uint32_t stB = stA + A_T2 * 2;

        if (hAcc) {
            // fp16 accumulators per iter (K=32 chunk), flushed to fp32
            #pragma unroll
            for (int mtg = 0; mtg < 2; mtg++) {
                unsigned hacc[2][4][2];
                #pragma unroll
                for (int a = 0; a < 2; a++)
                    #pragma unroll
                    for (int b = 0; b < 4; b++) { hacc[a][b][0] = 0u; hacc[a][b][1] = 0u; }
                #pragma unroll
                for (int kc = 0; kc < 2; kc++) {
                    unsigned bf[2][4];
                    #pragma unroll
                    for (int ntp = 0; ntp < 2; ntp++)
                        ldsm4t(bf[ntp][0], bf[ntp][1], bf[ntp][2], bf[ntp][3],
                               stB + (uint32_t)(kc * 16 * (BS2 * 2) + (32 * wn + ntp * 16) * 2) + bLane);
                    unsigned af[2][4];
                    #pragma unroll
                    for (int mt2 = 0; mt2 < 2; mt2++)
                        ldsm4(af[mt2][0], af[mt2][1], af[mt2][2], af[mt2][3],
                              stA + (uint32_t)((64 * wm + 16 * (2 * mtg + mt2)) * (AS2 * 2) + kc * 32) + aLane);
                    #pragma unroll
                    for (int mt2 = 0; mt2 < 2; mt2++)
                        #pragma unroll
                        for (int ntp = 0; ntp < 2; ntp++) {
                            mma16hh(hacc[mt2][2*ntp][0], hacc[mt2][2*ntp][1],
                                    af[mt2][0], af[mt2][1], af[mt2][2], af[mt2][3],
                                    bf[ntp][0], bf[ntp][1]);
                            mma16hh(hacc[mt2][2*ntp+1][0], hacc[mt2][2*ntp+1][1],
                                    af[mt2][0], af[mt2][1], af[mt2][2], af[mt2][3],
                                    bf[ntp][2], bf[ntp][3]);
                        }
                }
                // flush chunk into fp32 master
                #pragma unroll
                for (int mt2 = 0; mt2 < 2; mt2++)
                    #pragma unroll
                    for (int nt = 0; nt < 4; nt++) {
                        float2 lo = __half22float2(*(__half2*)&hacc[mt2][nt][0]);
                        float2 hi = __half22float2(*(__half2*)&hacc[mt2][nt][1]);
                        acc[2*mtg+mt2][nt][0] += lo.x;
                        acc[2*mtg+mt2][nt][1] += lo.y;
                        acc[2*mtg+mt2][nt][2] += hi.x;
                        acc[2*mtg+mt2][nt][3] += hi.y;
                    }
            }
        } else {
            #pragma unroll
            for (int kc = 0; kc < 2; kc++) {
                unsigned af[4][4];
                #pragma unroll
                for (int mt = 0; mt < 4; mt++)
                    ldsm4(af[mt][0], af[mt][1], af[mt][2], af[mt][3],
                          stA + (uint32_t)((64 * wm + 16 * mt) * (AS2 * 2) + kc * 32) + aLane);
                unsigned bf[2][4];
                #pragma unroll
                for (int ntp = 0; ntp < 2; ntp++)
                    ldsm4t(bf[ntp][0], bf[ntp][1], bf[ntp][2], bf[ntp][3],
                           stB + (uint32_t)(kc * 16 * (BS2 * 2) + (32 * wn + ntp * 16) * 2) + bLane);
                #pragma unroll
                for (int mt = 0; mt < 4; mt++)
                    #pragma unroll
                    for (int ntp = 0; ntp < 2; ntp++) {
                        mma16h(acc[mt][2*ntp][0], acc[mt][2*ntp][1], acc[mt][2*ntp][2], acc[mt][2*ntp][3],
                               af[mt][0], af[mt][1], af[mt][2], af[mt][3], bf[ntp][0], bf[ntp][1]);
                        mma16h(acc[mt][2*ntp+1][0], acc[mt][2*ntp+1][1], acc[mt][2*ntp+1][2], acc[mt][2*ntp+1][3],
                               af[mt][0], af[mt][1], af[mt][2], af[mt][3], bf[ntp][2], bf[ntp][3]);
                    }
            }
        }
    }

    #pragma unroll
    for (int mt = 0; mt < 4; mt++) {
        const int row = m0 + 64 * wm + 16 * mt + r;
        #pragma unroll
        for (int nt = 0; nt < 4; nt++) {
            const int col = n0 + 32 * wn + 8 * nt + 2 * c;
            float2 bz = *(const float2*)(bias + col);
            float2 o0 = { acc[mt][nt][0] + bz.x, acc[mt][nt][1] + bz.y };
            float2 o1 = { acc[mt][nt][2] + bz.x, acc[mt][nt][3] + bz.y };
            if (mode == 2) {
                *(__half2*)&Ch[(size_t)row * N + col] = __floats2half2_rn(o0.x * oscale, o0.y * oscale);
                *(__half2*)&Ch[(size_t)(row + 8) * N + col] = __floats2half2_rn(o1.x * oscale, o1.y * oscale);
            } else {
                *(float2*)&Cf[(size_t)row * N + col] = o0;
                *(float2*)&Cf[(size_t)(row + 8) * N + col] = o1;
            }
        }
    }
}

// merged Q/K/V/eq/ek projection: grid (64, 28)
__global__ __launch_bounds__(256, 2) void gemm_proj(
    const float* __restrict__ bq, const float* __restrict__ bk, const float* __restrict__ bv,
    const float* __restrict__ beq, const float* __restrict__ bek)
{
    extern __shared__ char smc[];
    const int y = blockIdx.y;
    const int m0 = blockIdx.x * 128;
    if (y < 24) {
        const int z = y >> 3, ny = y & 7;
        const __half* W = g_whr + (z == 0 ? OFF_WQ : (z == 1 ? OFF_WK : OFF_WV));
        const float* bias = z == 0 ? bq : (z == 1 ? bk : bv);
        __half* Ch = z == 0 ? g_qh : (z == 1 ? g_kh : g_vh);
        const float sc = z == 0 ? 0.125f * LOG2E : 1.0f;
        gemmh_body<1>(g_xh, W, bias, 0, Ch, Hh, Hh, 2, sc, m0, ny * 128, smc);
    } else {
        const int idx = y - 24, z = idx >> 1, ny = idx & 1;
        const __half* W = g_whr + (z == 0 ? OFF_WEQ : OFF_WEK);
        const float* bias = z == 0 ? beq : bek;
        __half* Ch = z == 0 ? g_eqh : g_ekh;
        gemmh_body<1>(g_xh, W, bias, 0, Ch, Ee, Hh, 2, 1.f, m0, ny * 128, smc);
    }
}

__global__ __launch_bounds__(256, 2) void gemm_out(
    const float* __restrict__ bias, float* __restrict__ C)
{
    extern __shared__ char smc[];
    gemmh_body<0>(g_ctxh, g_whr + OFF_WO, bias, C, 0, Hh, Hh, 0, 1.f,
                  blockIdx.x * 128, blockIdx.y * 128, smc);
}

// =============================================================================
// exp-bias GEMM (fp16 acc, 4-stage): g_biash = fp16(scale*log2e*eq.ek^T), K=256
// =============================================================================
#define EB2_STAGE (2*A_T2*2)
#define EBH_SMEM (4*EB2_STAGE)

__device__ __forceinline__ void eb_load(uint32_t sbase, const __half* A, const __half* Bm,
                                        int m0, int n0, int s, int tid)
{
    const uint32_t st = sbase + (uint32_t)((s & 3) * EB2_STAGE);
    const int kt = s * 32;
    #pragma unroll
    for (int i = 0; i < 2; i++) {
        int lin = tid + i * 256, row = lin >> 2, ch = (lin & 3) * 8;
        cp16(st + (uint32_t)(row * AS2 + ch) * 2, A + (size_t)(m0 + row) * Ee + kt + ch);
        cp16(st + (uint32_t)(A_T2 + row * AS2 + ch) * 2, Bm + (size_t)(n0 + row) * Ee + kt + ch);
    }
}

__global__ __launch_bounds__(256, 2) void expbias_h(const float* __restrict__ conf)
{
    extern __shared__ char smc[];
    const int b = blockIdx.z;
    const __half* A  = g_eqh + (size_t)b * Ss * Ee;
    const __half* Bm = g_ekh + (size_t)b * Ss * Ee;
    __half* C = g_biash + (size_t)b * Ss * Ss;
    const float scale = 0.3f * __ldg(&conf[b]) * (1.0f / 16.0f) * LOG2E;

    const int tid = threadIdx.x, lane = tid & 31, wid = tid >> 5;
    const int wm = wid >> 2, wn = wid & 3;
    const int r = lane >> 2, c = lane & 3;
    const int m0 = blockIdx.x * 128, n0 = blockIdx.y * 128;
    const uint32_t sbase = (uint32_t)__cvta_generic_to_shared(smc);

    float acc[4][4][4];
    #pragma unroll
    for (int i = 0; i < 4; i++)
        #pragma unroll
        for (int j = 0; j < 4; j++)
            #pragma unroll
            for (int q = 0; q < 4; q++) acc[i][j][q] = 0.f;

    const uint32_t aLane = (uint32_t)((lane & 15) * (AS2 * 2) + (lane >> 4) * 16);
    const uint32_t bLaneE = (uint32_t)((((lane >> 4) * 8 + (lane & 7)) * AS2) * 2 + ((lane >> 3) & 1) * 16);

    const int niter = Ee / 32;
    #pragma unroll
    for (int s = 0; s < 3; s++) { eb_load(sbase, A, Bm, m0, n0, s, tid); CP_COMMIT; }

    for (int it = 0; it < niter; it++) {
        if (it + 2 < niter) { CP_WAIT2; }
        else if (it + 1 < niter) { CP_WAIT1; }
        else { CP_WAIT0; }
        __syncthreads();

        if (it + 3 < niter) { eb_load(sbase, A, Bm, m0, n0, it + 3, tid); CP_COMMIT; }

        const uint32_t stA = sbase + (uint32_t)((it & 3) * EB2_STAGE);
        const uint32_t stB = stA + A_T2 * 2;

        #pragma unroll
        for (int mtg = 0; mtg < 2; mtg++) {
            unsigned hacc[2][4][2];
            #pragma unroll
            for (int a = 0; a < 2; a++)
                #pragma unroll
                for (int bq_ = 0; bq_ < 4; bq_++) { hacc[a][bq_][0] = 0u; hacc[a][bq_][1] = 0u; }
            #pragma unroll
            for (int kc = 0; kc < 2; kc++) {
                unsigned bf[2][4];
                #pragma unroll
                for (int ntp = 0; ntp < 2; ntp++)
                    ldsm4(bf[ntp][0], bf[ntp][1], bf[ntp][2], bf[ntp][3],
                          stB + (uint32_t)((32 * wn + ntp * 16) * (AS2 * 2) + kc * 32) + bLaneE);
                unsigned af[2][4];
                #pragma unroll
                for (int mt2 = 0; mt2 < 2; mt2++)
                    ldsm4(af[mt2][0], af[mt2][1], af[mt2][2], af[mt2][3],
                          stA + (uint32_t)((64 * wm + 16 * (2 * mtg + mt2)) * (AS2 * 2) + kc * 32) + aLane);
                #pragma unroll
                for (int mt2 = 0; mt2 < 2; mt2++)
                    #pragma unroll
                    for (int ntp = 0; ntp < 2; ntp++) {
                        mma16hh(hacc[mt2][2*ntp][0], hacc[mt2][2*ntp][1],
                                af[mt2][0], af[mt2][1], af[mt2][2], af[mt2][3],
                                bf[ntp][0], bf[ntp][1]);
                        mma16hh(hacc[mt2][2*ntp+1][0], hacc[mt2][2*ntp+1][1],
                                af[mt2][0], af[mt2][1], af[mt2][2], af[mt2][3],
                                bf[ntp][2], bf[ntp][3]);
                    }
            }
            #pragma unroll
            for (int mt2 = 0; mt2 < 2; mt2++)
                #pragma unroll
                for (int nt = 0; nt < 4; nt++) {
                    float2 lo = __half22float2(*(__half2*)&hacc[mt2][nt][0]);
                    float2 hi = __half22float2(*(__half2*)&hacc[mt2][nt][1]);
                    acc[2*mtg+mt2][nt][0] += lo.x;
                    acc[2*mtg+mt2][nt][1] += lo.y;
                    acc[2*mtg+mt2][nt][2] += hi.x;
                    acc[2*mtg+mt2][nt][3] += hi.y;
                }
        }
    }

    #pragma unroll
    for (int mt = 0; mt < 4; mt++) {
        const int row = m0 + 64 * wm + 16 * mt + r;
        #pragma unroll
        for (int nt = 0; nt < 4; nt++) {
            const int col = n0 + 32 * wn + 8 * nt + 2 * c;
            *(__half2*)&C[(size_t)row * Ss + col] =
                __floats2half2_rn(acc[mt][nt][0] * scale, acc[mt][nt][1] * scale);
            *(__half2*)&C[(size_t)(row + 8) * Ss + col] =
                __floats2half2_rn(acc[mt][nt][2] * scale, acc[mt][nt][3] * scale);
        }
    }
}

// =============================================================================
// fp16 flash attention (unchanged from R13): f16-acc QK, ex2.f16x2,
// ones-column row sums, fp32-acc PV, 2 CTAs/SM.
// =============================================================================
#define KSh 72
#define BSh 72
#define V_OFFB (64*KSh*2)
#define B_OFFB (2*64*KSh*2)
#define STAGE_B (2*64*KSh*2 + 128*BSh*2)
#define ATTN_SMEM (2*STAGE_B)
#define ONES2 0x3C003C00u

__global__ __launch_bounds__(256, 2) void attn_h()
{
    extern __shared__ char smc[];
    const int tid = threadIdx.x, lane = tid & 31, wid = tid >> 5;
    const int r = lane >> 2, c = lane & 3;
    const int q0 = blockIdx.x * 128, h = blockIdx.y, b = blockIdx.z;
    const uint32_t sbase = (uint32_t)__cvta_generic_to_shared(smc);

    const __half* gq = g_qh + ((size_t)(b * Ss + q0)) * Hh + h * HD;
    #pragma unroll
    for (int i = 0; i < 4; i++) {
        int lin = tid + i * 256, row = lin >> 3, ch = (lin & 7) * 8;
        cp16(sbase + (uint32_t)(row * KSh + ch) * 2, gq + (size_t)row * Hh + ch);
    }
    CP_COMMIT; CP_WAIT0;
    __syncthreads();

    unsigned qf[4][4];
    {
        const __half* Qs = (const __half*)smc;
        #pragma unroll
        for (int kc = 0; kc < 4; kc++) {
            const int idx = (16 * wid + r) * KSh + kc * 16 + 2 * c;
            qf[kc][0] = *(const unsigned*)&Qs[idx];
            qf[kc][1] = *(const unsigned*)&Qs[idx + 8 * KSh];
            qf[kc][2] = *(const unsigned*)&Qs[idx + 8];
            qf[kc][3] = *(const unsigned*)&Qs[idx + 8 * KSh + 8];
        }
    }
    __syncthreads();

    const __half* bias_base = g_biash + ((size_t)b * Ss + q0) * Ss;
    const size_t kv_base = (size_t)(b * Ss) * Hh + h * HD;

    {
        const uint32_t st = sbase;
        #pragma unroll
        for (int i = 0; i < 2; i++) {
            int lin = tid + i * 256, row = lin >> 3, ch = (lin & 7) * 8;
            size_t go = kv_base + (size_t)row * Hh + ch;
            cp16(st + (uint32_t)(row * KSh + ch) * 2, g_kh + go);
            cp16(st + V_OFFB + (uint32_t)(row * KSh + ch) * 2, g_vh + go);
        }
        #pragma unroll
        for (int i = 0; i < 4; i++) {
            int lin = tid + i * 256, row = lin >> 3, ch = (lin & 7) * 8;
            cp16(st + B_OFFB + (uint32_t)(row * BSh + ch) * 2, bias_base + (size_t)row * Ss + ch);
        }
        CP_COMMIT;
    }

    float oacc[8][4];
    #pragma unroll
    for (int i = 0; i < 8; i++)
        #pragma unroll
        for (int j = 0; j < 4; j++) oacc[i][j] = 0.f;
    float sumacc[4] = {0.f, 0.f, 0.f, 0.f};

    const uint32_t klane4 = (uint32_t)((((lane >> 4) * 8 + (lane & 7)) * KSh) * 2 + ((lane >> 3) & 1) * 16);
    const uint32_t vlane4 = (uint32_t)(((lane & 15) * KSh) * 2 + (lane >> 4) * 16);

    const int NT = Ss / 64;
    for (int kt = 0; kt < NT; kt++) {
        CP_WAIT0;
        __syncthreads();

        if (kt + 1 < NT) {
            const int k1 = (kt + 1) * 64;
            const uint32_t st = sbase + (uint32_t)(((kt + 1) & 1) * STAGE_B);
            #pragma unroll
            for (int i = 0; i < 2; i++) {
                int lin = tid + i * 256, row = lin >> 3, ch = (lin & 7) * 8;
                size_t go = kv_base + (size_t)(k1 + row) * Hh + ch;
                cp16(st + (uint32_t)(row * KSh + ch) * 2, g_kh + go);
                cp16(st + V_OFFB + (uint32_t)(row * KSh + ch) * 2, g_vh + go);
            }
            #pragma unroll
            for (int i = 0; i < 4; i++) {
                int lin = tid + i * 256, row = lin >> 3, ch = (lin & 7) * 8;
                cp16(st + B_OFFB + (uint32_t)(row * BSh + ch) * 2,
                     bias_base + (size_t)row * Ss + k1 + ch);
            }
            CP_COMMIT;
        }

        const uint32_t stage = sbase + (uint32_t)((kt & 1) * STAGE_B);
        const uint32_t kBase = stage + klane4;
        const uint32_t vBase = stage + V_OFFB + vlane4;
        const __half* Bs_ = (const __half*)(smc + (kt & 1) * STAGE_B + B_OFFB);

        unsigned sacc[8][2];
        #pragma unroll
        for (int nt = 0; nt < 8; nt++) {
            sacc[nt][0] = *(const unsigned*)&Bs_[(16 * wid + r) * BSh + 8 * nt + 2 * c];
            sacc[nt][1] = *(const unsigned*)&Bs_[(16 * wid + r + 8) * BSh + 8 * nt + 2 * c];
        }

        #pragma unroll
        for (int kc = 0; kc < 4; kc++) {
            #pragma unroll
            for (int ntp = 0; ntp < 4; ntp++) {
                unsigned b0, b1, b2, b3;
                ldsm4(b0, b1, b2, b3, kBase + (uint32_t)(ntp * (16 * KSh * 2) + kc * 32));
                mma16hh(sacc[2*ntp][0], sacc[2*ntp][1],
                        qf[kc][0], qf[kc][1], qf[kc][2], qf[kc][3], b0, b1);
                mma16hh(sacc[2*ntp+1][0], sacc[2*ntp+1][1],
                        qf[kc][0], qf[kc][1], qf[kc][2], qf[kc][3], b2, b3);
            }
        }

        #pragma unroll
        for (int j = 0; j < 4; j++) {
            unsigned a0 = h2ex2(sacc[2*j][0]);
            unsigned a1 = h2ex2(sacc[2*j][1]);
            unsigned a2 = h2ex2(sacc[2*j+1][0]);
            unsigned a3 = h2ex2(sacc[2*j+1][1]);
            mma16h(sumacc[0], sumacc[1], sumacc[2], sumacc[3],
                   a0, a1, a2, a3, ONES2, ONES2);
            #pragma unroll
            for (int ntp = 0; ntp < 4; ntp++) {
                unsigned b0, b1, b2, b3;
                ldsm4t(b0, b1, b2, b3, vBase + (uint32_t)(j * (16 * KSh * 2) + ntp * 32));
                mma16h(oacc[2*ntp][0], oacc[2*ntp][1], oacc[2*ntp][2], oacc[2*ntp][3],
                       a0, a1, a2, a3, b0, b1);
                mma16h(oacc[2*ntp+1][0], oacc[2*ntp+1][1], oacc[2*ntp+1][2], oacc[2*ntp+1][3],
                       a0, a1, a2, a3, b2, b3);
            }
        }
    }

    const float inv0 = 1.0f / sumacc[0], inv1 = 1.0f / sumacc[2];
    const int row = q0 + 16 * wid + r;
    #pragma unroll
    for (int nt = 0; nt < 8; nt++) {
        const int col = h * HD + 8 * nt + 2 * c;
        *(__half2*)&g_ctxh[((size_t)(b * Ss + row)) * Hh + col] =
            __floats2half2_rn(oacc[nt][0] * inv0, oacc[nt][1] * inv0);
        *(__half2*)&g_ctxh[((size_t)(b * Ss + row + 8)) * Hh + col] =
            __floats2half2_rn(oacc[nt][2] * inv1, oacc[nt][3] * inv1);
    }
}

// ---------------- launch ------------------------------------------------------
extern "C" void kernel_launch(void* const* d_in, const int* in_sizes, int n_in,
                              void* d_out, int out_size)
{
    const float* x    = (const float*)d_in[0];
    const float* conf = (const float*)d_in[1];
    const float* Wq   = (const float*)d_in[2];
    const float* bq   = (const float*)d_in[3];
    const float* Wk   = (const float*)d_in[4];
    const float* bk   = (const float*)d_in[5];
    const float* Wv   = (const float*)d_in[6];
    const float* bv   = (const float*)d_in[7];
    const float* Weq  = (const float*)d_in[8];
    const float* beq  = (const float*)d_in[9];
    const float* Wek  = (const float*)d_in[10];
    const float* bek  = (const float*)d_in[11];
    const float* Wo   = (const float*)d_in[12];
    const float* bo   = (const float*)d_in[13];
    float* out = (float*)d_out;

    __half *pxh, *pwh;
    cudaGetSymbolAddress((void**)&pxh, g_xh);
    cudaGetSymbolAddress((void**)&pwh, g_whr);

    cudaFuncSetAttribute(gemm_proj, cudaFuncAttributeMaxDynamicSharedMemorySize, GEMMH_SMEM);
    cudaFuncSetAttribute(gemm_out,  cudaFuncAttributeMaxDynamicSharedMemorySize, GEMMH_SMEM);
    cudaFuncSetAttribute(expbias_h, cudaFuncAttributeMaxDynamicSharedMemorySize, EBH_SMEM);
    cudaFuncSetAttribute(attn_h,    cudaFuncAttributeMaxDynamicSharedMemorySize, ATTN_SMEM);

    dim3 blk(256);

    round_h<<<(Mm * Hh / 4 + 255) / 256, blk>>>(x, pxh, Mm * Hh / 4);
    round_w<<<dim3(Hh * Hh / 4 / 256, 6), blk>>>(Wq, Wk, Wv, Wo, Weq, Wek, pwh);

    gemm_proj<<<dim3(Mm / 128, 28), blk, GEMMH_SMEM>>>(bq, bk, bv, beq, bek);
    expbias_h<<<dim3(Ss / 128, Ss / 128, Bb), blk, EBH_SMEM>>>(conf);
    attn_h<<<dim3(Ss / 128, NH, Bb), blk, ATTN_SMEM>>>();
    gemm_out<<<dim3(Mm / 128, Hh / 128), blk, GEMMH_SMEM>>>(bo, out);
}

// round 15
// speedup vs baseline: 1.0821x; 1.0821x over previous
#include <cuda_runtime.h>
#include <cuda_fp16.h>
#include <math.h>
#include <stdint.h>

#define Bb 4
#define Ss 2048
#define Hh 1024
#define NH 16
#define HD 64
#define Ee 256
#define Mm (Bb*Ss)
#define LOG2E 1.44269504f

// ---------------- static device scratch -------------------------------------
__device__ __half g_qh[(size_t)Mm*Hh];   // fp16 Q (pre-scaled by 0.125*log2e)
__device__ __half g_kh[(size_t)Mm*Hh];
__device__ __half g_vh[(size_t)Mm*Hh];
__device__ __half g_eqh[(size_t)Mm*Ee];
__device__ __half g_ekh[(size_t)Mm*Ee];
__device__ __half g_biash[(size_t)Bb*Ss*Ss];  // bias pre-scaled by log2e
__device__ __half g_ctxh[(size_t)Mm*Hh];
__device__ __half g_xh[(size_t)Mm*Hh];
__device__ __half g_whr[(size_t)4*Hh*Hh + 2*Hh*Ee];

#define OFF_WQ  ((size_t)0)
#define OFF_WK  ((size_t)1*Hh*Hh)
#define OFF_WV  ((size_t)2*Hh*Hh)
#define OFF_WO  ((size_t)3*Hh*Hh)
#define OFF_WEQ ((size_t)4*Hh*Hh)
#define OFF_WEK ((size_t)4*Hh*Hh + (size_t)Hh*Ee)

// ---------------- helpers ----------------------------------------------------
__device__ __forceinline__ void mma16h(float& c0, float& c1, float& c2, float& c3,
                                       unsigned a0, unsigned a1, unsigned a2, unsigned a3,
                                       unsigned b0, unsigned b1) {
    asm volatile("mma.sync.aligned.m16n8k16.row.col.f32.f16.f16.f32 "
                 "{%0,%1,%2,%3},{%4,%5,%6,%7},{%8,%9},{%0,%1,%2,%3};"
                 : "+f"(c0), "+f"(c1), "+f"(c2), "+f"(c3)
                 : "r"(a0), "r"(a1), "r"(a2), "r"(a3), "r"(b0), "r"(b1));
}
// fp16-accumulate variant (C/D = 2x f16x2 regs)
__device__ __forceinline__ void mma16hh(unsigned& c0, unsigned& c1,
                                        unsigned a0, unsigned a1, unsigned a2, unsigned a3,
                                        unsigned b0, unsigned b1) {
    asm volatile("mma.sync.aligned.m16n8k16.row.col.f16.f16.f16.f16 "
                 "{%0,%1},{%2,%3,%4,%5},{%6,%7},{%0,%1};"
                 : "+r"(c0), "+r"(c1)
                 : "r"(a0), "r"(a1), "r"(a2), "r"(a3), "r"(b0), "r"(b1));
}
__device__ __forceinline__ void cp16(uint32_t dst, const void* src) {
    asm volatile("cp.async.ca.shared.global [%0], [%1], 16;" :: "r"(dst), "l"(src));
}
__device__ __forceinline__ void ldsm4(unsigned& r0, unsigned& r1, unsigned& r2, unsigned& r3, uint32_t a) {
    asm volatile("ldmatrix.sync.aligned.m8n8.x4.shared.b16 {%0,%1,%2,%3}, [%4];"
                 : "=r"(r0), "=r"(r1), "=r"(r2), "=r"(r3) : "r"(a));
}
__device__ __forceinline__ void ldsm4t(unsigned& r0, unsigned& r1, unsigned& r2, unsigned& r3, uint32_t a) {
    asm volatile("ldmatrix.sync.aligned.m8n8.x4.trans.shared.b16 {%0,%1,%2,%3}, [%4];"
                 : "=r"(r0), "=r"(r1), "=r"(r2), "=r"(r3) : "r"(a));
}
__device__ __forceinline__ unsigned h2ex2(unsigned x) {
    unsigned d; asm("ex2.approx.f16x2 %0, %1;" : "=r"(d) : "r"(x)); return d;
}
#define CP_COMMIT asm volatile("cp.async.commit_group;")
#define CP_WAIT2  asm volatile("cp.async.wait_group 2;")
#define CP_WAIT1  asm volatile("cp.async.wait_group 1;")
#define CP_WAIT0  asm volatile("cp.async.wait_group 0;")

// ---------------- fp32 -> fp16 conversion (x + all 6 weights, one launch) ------
__global__ __launch_bounds__(256) void round_all(
    const float* __restrict__ x,
    const float* __restrict__ w0, const float* __restrict__ w1,
    const float* __restrict__ w2, const float* __restrict__ w3,
    const float* __restrict__ w4, const float* __restrict__ w5,
    __half* __restrict__ xout, __half* __restrict__ wout)
{
    const int z = blockIdx.y;
    const float* src;
    __half* dst; int n4;
    switch (z) {
        case 0: src = x;  dst = xout;            n4 = Mm * Hh / 4; break;
        case 1: src = w0; dst = wout + OFF_WQ;   n4 = Hh * Hh / 4; break;
        case 2: src = w1; dst = wout + OFF_WK;   n4 = Hh * Hh / 4; break;
        case 3: src = w2; dst = wout + OFF_WV;   n4 = Hh * Hh / 4; break;
        case 4: src = w3; dst = wout + OFF_WO;   n4 = Hh * Hh / 4; break;
        case 5: src = w4; dst = wout + OFF_WEQ;  n4 = Hh * Ee / 4; break;
        default: src = w5; dst = wout + OFF_WEK; n4 = Hh * Ee / 4; break;
    }
    int i = blockIdx.x * 256 + threadIdx.x;
    if (i < n4) {
        float4 v = ((const float4*)src)[i];
        __half2* o = (__half2*)dst + 2 * (size_t)i;
        o[0] = __floats2half2_rn(v.x, v.y);
        o[1] = __floats2half2_rn(v.z, v.w);
    }
}

// =============================================================================
// fp16 GEMM core: C = A[M,K]h @ W[K,N]h + bias[N]f   (4-stage cp.async, fp32 acc)
// =============================================================================
#define AS2 40
#define BS2 136
#define A_T2 (128*AS2)
#define B_T2 (32*BS2)
#define G2_STAGE ((A_T2 + B_T2)*2)
#define GEMMH_SMEM (4*G2_STAGE)

__device__ __forceinline__ void g_load(uint32_t sbase, const __half* A, const __half* W,
                                       int N, int K, int m0, int n0, int s, int tid)
{
    const uint32_t st = sbase + (uint32_t)((s & 3) * G2_STAGE);
    const int kt = s * 32;
    #pragma unroll
    for (int i = 0; i < 2; i++) {
        int lin = tid + i * 256, row = lin >> 2, ch = (lin & 3) * 8;
        cp16(st + (uint32_t)(row * AS2 + ch) * 2, A + (size_t)(m0 + row) * K + kt + ch);
    }
    #pragma unroll
    for (int i = 0; i < 2; i++) {
        int lin = tid + i * 256, row = lin >> 4, ch = (lin & 15) * 8;
        cp16(st + (uint32_t)(A_T2 + row * BS2 + ch) * 2, W + (size_t)(kt + row) * N + n0 + ch);
    }
}

__device__ __forceinline__ void gemmh_body(
    const __half* __restrict__ A, const __half* __restrict__ W,
    const float* __restrict__ bias, float* __restrict__ Cf, __half* __restrict__ Ch,
    int N, int K, int mode, float oscale, int m0, int n0, char* smc)
{
    const int tid = threadIdx.x, lane = tid & 31, wid = tid >> 5;
    const int wm = wid >> 2, wn = wid & 3;
    const int r = lane >> 2, c = lane & 3;
    const uint32_t sbase = (uint32_t)__cvta_generic_to_shared(smc);

    float acc[4][4][4];
    #pragma unroll
    for (int i = 0; i < 4; i++)
        #pragma unroll
        for (int j = 0; j < 4; j++)
            #pragma unroll
            for (int q = 0; q < 4; q++) acc[i][j][q] = 0.f;

    const uint32_t aLane = (uint32_t)((lane & 15) * (AS2 * 2) + (lane >> 4) * 16);
    const uint32_t bLane = (uint32_t)((lane & 15) * (BS2 * 2) + (lane >> 4) * 16);

    const int niter = K / 32;
    #pragma unroll
    for (int s = 0; s < 3; s++) { g_load(sbase, A, W, N, K, m0, n0, s, tid); CP_COMMIT; }

    for (int it = 0; it < niter; it++) {
        if (it + 2 < niter) { CP_WAIT2; }
        else if (it + 1 < niter) { CP_WAIT1; }
        else { CP_WAIT0; }
        __syncthreads();

        if (it + 3 < niter) { g_load(sbase, A, W, N, K, m0, n0, it + 3, tid); CP_COMMIT; }

        const uint32_t stA = sbase + (uint32_t)((it & 3) * G2_STAGE);
        const uint32_t stB = stA + A_T2 * 2;
        #pragma unroll
        for (int kc = 0; kc < 2; kc++) {
            unsigned af[4][4];
            #pragma unroll
            for (int mt = 0; mt < 4; mt++)
                ldsm4(af[mt][0], af[mt][1], af[mt][2], af[mt][3],
                      stA + (uint32_t)((64 * wm + 16 * mt) * (AS2 * 2) + kc * 32) + aLane);
            unsigned bf[2][4];
            #pragma unroll
            for (int ntp = 0; ntp < 2; ntp++)
                ldsm4t(bf[ntp][0], bf[ntp][1], bf[ntp][2], bf[ntp][3],
                       stB + (uint32_t)(kc * 16 * (BS2 * 2) + (32 * wn + ntp * 16) * 2) + bLane);
            #pragma unroll
            for (int mt = 0; mt < 4; mt++)
                #pragma unroll
                for (int ntp = 0; ntp < 2; ntp++) {
                    mma16h(acc[mt][2*ntp][0], acc[mt][2*ntp][1], acc[mt][2*ntp][2], acc[mt][2*ntp][3],
                           af[mt][0], af[mt][1], af[mt][2], af[mt][3], bf[ntp][0], bf[ntp][1]);
                    mma16h(acc[mt][2*ntp+1][0], acc[mt][2*ntp+1][1], acc[mt][2*ntp+1][2], acc[mt][2*ntp+1][3],
                           af[mt][0], af[mt][1], af[mt][2], af[mt][3], bf[ntp][2], bf[ntp][3]);
                }
        }
    }

    #pragma unroll
    for (int mt = 0; mt < 4; mt++) {
        const int row = m0 + 64 * wm + 16 * mt + r;
        #pragma unroll
        for (int nt = 0; nt < 4; nt++) {
            const int col = n0 + 32 * wn + 8 * nt + 2 * c;
            float2 bz = *(const float2*)(bias + col);
            float2 o0 = { acc[mt][nt][0] + bz.x, acc[mt][nt][1] + bz.y };
            float2 o1 = { acc[mt][nt][2] + bz.x, acc[mt][nt][3] + bz.y };
            if (mode == 2) {
                *(__half2*)&Ch[(size_t)row * N + col] = __floats2half2_rn(o0.x * oscale, o0.y * oscale);
                *(__half2*)&Ch[(size_t)(row + 8) * N + col] = __floats2half2_rn(o1.x * oscale, o1.y * oscale);
            } else {
                *(float2*)&Cf[(size_t)row * N + col] = o0;
                *(float2*)&Cf[(size_t)(row + 8) * N + col] = o1;
            }
        }
    }
}

// merged Q/K/V/eq/ek projection: grid (64, 28)
__global__ __launch_bounds__(256, 2) void gemm_proj(
    const float* __restrict__ bq, const float* __restrict__ bk, const float* __restrict__ bv,
    const float* __restrict__ beq, const float* __restrict__ bek)
{
    extern __shared__ char smc[];
    const int y = blockIdx.y;
    const int m0 = blockIdx.x * 128;
    if (y < 24) {
        const int z = y >> 3, ny = y & 7;
        const __half* W = g_whr + (z == 0 ? OFF_WQ : (z == 1 ? OFF_WK : OFF_WV));
        const float* bias = z == 0 ? bq : (z == 1 ? bk : bv);
        __half* Ch = z == 0 ? g_qh : (z == 1 ? g_kh : g_vh);
        const float sc = z == 0 ? 0.125f * LOG2E : 1.0f;
        gemmh_body(g_xh, W, bias, 0, Ch, Hh, Hh, 2, sc, m0, ny * 128, smc);
    } else {
        const int idx = y - 24, z = idx >> 1, ny = idx & 1;
        const __half* W = g_whr + (z == 0 ? OFF_WEQ : OFF_WEK);
        const float* bias = z == 0 ? beq : bek;
        __half* Ch = z == 0 ? g_eqh : g_ekh;
        gemmh_body(g_xh, W, bias, 0, Ch, Ee, Hh, 2, 1.f, m0, ny * 128, smc);
    }
}

__global__ __launch_bounds__(256, 2) void gemm_out(
    const float* __restrict__ bias, float* __restrict__ C)
{
    extern __shared__ char smc[];
    gemmh_body(g_ctxh, g_whr + OFF_WO, bias, C, 0, Hh, Hh, 0, 1.f,
               blockIdx.x * 128, blockIdx.y * 128, smc);
}

// =============================================================================
// exp-bias GEMM (fp32 acc, 4-stage): g_biash = fp16(scale*log2e*eq.ek^T), K=256
// =============================================================================
#define EB2_STAGE (2*A_T2*2)
#define EBH_SMEM (4*EB2_STAGE)

__device__ __forceinline__ void eb_load(uint32_t sbase, const __half* A, const __half* Bm,
                                        int m0, int n0, int s, int tid)
{
    const uint32_t st = sbase + (uint32_t)((s & 3) * EB2_STAGE);
    const int kt = s * 32;
    #pragma unroll
    for (int i = 0; i < 2; i++) {
        int lin = tid + i * 256, row = lin >> 2, ch = (lin & 3) * 8;
        cp16(st + (uint32_t)(row * AS2 + ch) * 2, A + (size_t)(m0 + row) * Ee + kt + ch);
        cp16(st + (uint32_t)(A_T2 + row * AS2 + ch) * 2, Bm + (size_t)(n0 + row) * Ee + kt + ch);
    }
}

__global__ __launch_bounds__(256, 2) void expbias_h(const float* __restrict__ conf)
{
    extern __shared__ char smc[];
    const int b = blockIdx.z;
    const __half* A  = g_eqh + (size_t)b * Ss * Ee;
    const __half* Bm = g_ekh + (size_t)b * Ss * Ee;
    __half* C = g_biash + (size_t)b * Ss * Ss;
    const float scale = 0.3f * __ldg(&conf[b]) * (1.0f / 16.0f) * LOG2E;

    const int tid = threadIdx.x, lane = tid & 31, wid = tid >> 5;
    const int wm = wid >> 2, wn = wid & 3;
    const int r = lane >> 2, c = lane & 3;
    const int m0 = blockIdx.x * 128, n0 = blockIdx.y * 128;
    const uint32_t sbase = (uint32_t)__cvta_generic_to_shared(smc);

    float acc[4][4][4];
    #pragma unroll
    for (int i = 0; i < 4; i++)
        #pragma unroll
        for (int j = 0; j < 4; j++)
            #pragma unroll
            for (int q = 0; q < 4; q++) acc[i][j][q] = 0.f;

    const uint32_t aLane = (uint32_t)((lane & 15) * (AS2 * 2) + (lane >> 4) * 16);
    const uint32_t bLaneE = (uint32_t)((((lane >> 4) * 8 + (lane & 7)) * AS2) * 2 + ((lane >> 3) & 1) * 16);

    const int niter = Ee / 32;
    #pragma unroll
    for (int s = 0; s < 3; s++) { eb_load(sbase, A, Bm, m0, n0, s, tid); CP_COMMIT; }

    for (int it = 0; it < niter; it++) {
        if (it + 2 < niter) { CP_WAIT2; }
        else if (it + 1 < niter) { CP_WAIT1; }
        else { CP_WAIT0; }
        __syncthreads();

        if (it + 3 < niter) { eb_load(sbase, A, Bm, m0, n0, it + 3, tid); CP_COMMIT; }

        const uint32_t stA = sbase + (uint32_t)((it & 3) * EB2_STAGE);
        const uint32_t stB = stA + A_T2 * 2;
        #pragma unroll
        for (int kc = 0; kc < 2; kc++) {
            unsigned af[4][4];
            #pragma unroll
            for (int mt = 0; mt < 4; mt++)
                ldsm4(af[mt][0], af[mt][1], af[mt][2], af[mt][3],
                      stA + (uint32_t)((64 * wm + 16 * mt) * (AS2 * 2) + kc * 32) + aLane);
            unsigned bf[2][4];
            #pragma unroll
            for (int ntp = 0; ntp < 2; ntp++)
                ldsm4(bf[ntp][0], bf[ntp][1], bf[ntp][2], bf[ntp][3],
                      stB + (uint32_t)((32 * wn + ntp * 16) * (AS2 * 2) + kc * 32) + bLaneE);
            #pragma unroll
            for (int mt = 0; mt < 4; mt++)
                #pragma unroll
                for (int ntp = 0; ntp < 2; ntp++) {
                    mma16h(acc[mt][2*ntp][0], acc[mt][2*ntp][1], acc[mt][2*ntp][2], acc[mt][2*ntp][3],
                           af[mt][0], af[mt][1], af[mt][2], af[mt][3], bf[ntp][0], bf[ntp][1]);
                    mma16h(acc[mt][2*ntp+1][0], acc[mt][2*ntp+1][1], acc[mt][2*ntp+1][2], acc[mt][2*ntp+1][3],
                           af[mt][0], af[mt][1], af[mt][2], af[mt][3], bf[ntp][2], bf[ntp][3]);
                }
        }
    }

    #pragma unroll
    for (int mt = 0; mt < 4; mt++) {
        const int row = m0 + 64 * wm + 16 * mt + r;
        #pragma unroll
        for (int nt = 0; nt < 4; nt++) {
            const int col = n0 + 32 * wn + 8 * nt + 2 * c;
            *(__half2*)&C[(size_t)row * Ss + col] =
                __floats2half2_rn(acc[mt][nt][0] * scale, acc[mt][nt][1] * scale);
            *(__half2*)&C[(size_t)(row + 8) * Ss + col] =
                __floats2half2_rn(acc[mt][nt][2] * scale, acc[mt][nt][3] * scale);
        }
    }
}

// =============================================================================
// fp16 flash attention (R13): f16-acc QK (bias loads straight into acc),
// ex2.f16x2 on accumulator frags, ones-column row sums, fp32-acc PV, 2 CTAs/SM.
// =============================================================================
#define KSh 72
#define BSh 72
#define V_OFFB (64*KSh*2)
#define B_OFFB (2*64*KSh*2)
#define STAGE_B (2*64*KSh*2 + 128*BSh*2)
#define ATTN_SMEM (2*STAGE_B)
#define ONES2 0x3C003C00u

__global__ __launch_bounds__(256, 2) void attn_h()
{
    extern __shared__ char smc[];
    const int tid = threadIdx.x, lane = tid & 31, wid = tid >> 5;
    const int r = lane >> 2, c = lane & 3;
    const int q0 = blockIdx.x * 128, h = blockIdx.y, b = blockIdx.z;
    const uint32_t sbase = (uint32_t)__cvta_generic_to_shared(smc);

    const __half* gq = g_qh + ((size_t)(b * Ss + q0)) * Hh + h * HD;
    #pragma unroll
    for (int i = 0; i < 4; i++) {
        int lin = tid + i * 256, row = lin >> 3, ch = (lin & 7) * 8;
        cp16(sbase + (uint32_t)(row * KSh + ch) * 2, gq + (size_t)row * Hh + ch);
    }
    CP_COMMIT; CP_WAIT0;
    __syncthreads();

    unsigned qf[4][4];
    {
        const __half* Qs = (const __half*)smc;
        #pragma unroll
        for (int kc = 0; kc < 4; kc++) {
            const int idx = (16 * wid + r) * KSh + kc * 16 + 2 * c;
            qf[kc][0] = *(const unsigned*)&Qs[idx];
            qf[kc][1] = *(const unsigned*)&Qs[idx + 8 * KSh];
            qf[kc][2] = *(const unsigned*)&Qs[idx + 8];
            qf[kc][3] = *(const unsigned*)&Qs[idx + 8 * KSh + 8];
        }
    }
    __syncthreads();

    const __half* bias_base = g_biash + ((size_t)b * Ss + q0) * Ss;
    const size_t kv_base = (size_t)(b * Ss) * Hh + h * HD;

    {
        const uint32_t st = sbase;
        #pragma unroll
        for (int i = 0; i < 2; i++) {
            int lin = tid + i * 256, row = lin >> 3, ch = (lin & 7) * 8;
            size_t go = kv_base + (size_t)row * Hh + ch;
            cp16(st + (uint32_t)(row * KSh + ch) * 2, g_kh + go);
            cp16(st + V_OFFB + (uint32_t)(row * KSh + ch) * 2, g_vh + go);
        }
        #pragma unroll
        for (int i = 0; i < 4; i++) {
            int lin = tid + i * 256, row = lin >> 3, ch = (lin & 7) * 8;
            cp16(st + B_OFFB + (uint32_t)(row * BSh + ch) * 2, bias_base + (size_t)row * Ss + ch);
        }
        CP_COMMIT;
    }

    float oacc[8][4];
    #pragma unroll
    for (int i = 0; i < 8; i++)
        #pragma unroll
        for (int j = 0; j < 4; j++) oacc[i][j] = 0.f;
    float sumacc[4] = {0.f, 0.f, 0.f, 0.f};

    const uint32_t klane4 = (uint32_t)((((lane >> 4) * 8 + (lane & 7)) * KSh) * 2 + ((lane >> 3) & 1) * 16);
    const uint32_t vlane4 = (uint32_t)(((lane & 15) * KSh) * 2 + (lane >> 4) * 16);

    const int NT = Ss / 64;
    for (int kt = 0; kt < NT; kt++) {
        CP_WAIT0;
        __syncthreads();

        if (kt + 1 < NT) {
            const int k1 = (kt + 1) * 64;
            const uint32_t st = sbase + (uint32_t)(((kt + 1) & 1) * STAGE_B);
            #pragma unroll
            for (int i = 0; i < 2; i++) {
                int lin = tid + i * 256, row = lin >> 3, ch = (lin & 7) * 8;
                size_t go = kv_base + (size_t)(k1 + row) * Hh + ch;
                cp16(st + (uint32_t)(row * KSh + ch) * 2, g_kh + go);
                cp16(st + V_OFFB + (uint32_t)(row * KSh + ch) * 2, g_vh + go);
            }
            #pragma unroll
            for (int i = 0; i < 4; i++) {
                int lin = tid + i * 256, row = lin >> 3, ch = (lin & 7) * 8;
                cp16(st + B_OFFB + (uint32_t)(row * BSh + ch) * 2,
                     bias_base + (size_t)row * Ss + k1 + ch);
            }
            CP_COMMIT;
        }

        const uint32_t stage = sbase + (uint32_t)((kt & 1) * STAGE_B);
        const uint32_t kBase = stage + klane4;
        const uint32_t vBase = stage + V_OFFB + vlane4;
        const __half* Bs_ = (const __half*)(smc + (kt & 1) * STAGE_B + B_OFFB);

        // init f16x2 score accumulators directly from fp16 bias (no conversion)
        unsigned sacc[8][2];
        #pragma unroll
        for (int nt = 0; nt < 8; nt++) {
            sacc[nt][0] = *(const unsigned*)&Bs_[(16 * wid + r) * BSh + 8 * nt + 2 * c];
            sacc[nt][1] = *(const unsigned*)&Bs_[(16 * wid + r + 8) * BSh + 8 * nt + 2 * c];
        }

        // S2 = (Q*log2e/8) @ K^T + bias  -- fp16 accumulate (K=64 chain only)
        #pragma unroll
        for (int kc = 0; kc < 4; kc++) {
            #pragma unroll
            for (int ntp = 0; ntp < 4; ntp++) {
                unsigned b0, b1, b2, b3;
                ldsm4(b0, b1, b2, b3, kBase + (uint32_t)(ntp * (16 * KSh * 2) + kc * 32));
                mma16hh(sacc[2*ntp][0], sacc[2*ntp][1],
                        qf[kc][0], qf[kc][1], qf[kc][2], qf[kc][3], b0, b1);
                mma16hh(sacc[2*ntp+1][0], sacc[2*ntp+1][1],
                        qf[kc][0], qf[kc][1], qf[kc][2], qf[kc][3], b2, b3);
            }
        }

        // p = 2^s on the accumulator frags; row sums via ones-MMA; O += P @ V
        #pragma unroll
        for (int j = 0; j < 4; j++) {
            unsigned a0 = h2ex2(sacc[2*j][0]);
            unsigned a1 = h2ex2(sacc[2*j][1]);
            unsigned a2 = h2ex2(sacc[2*j+1][0]);
            unsigned a3 = h2ex2(sacc[2*j+1][1]);
            mma16h(sumacc[0], sumacc[1], sumacc[2], sumacc[3],
                   a0, a1, a2, a3, ONES2, ONES2);
            #pragma unroll
            for (int ntp = 0; ntp < 4; ntp++) {
                unsigned b0, b1, b2, b3;
                ldsm4t(b0, b1, b2, b3, vBase + (uint32_t)(j * (16 * KSh * 2) + ntp * 32));
                mma16h(oacc[2*ntp][0], oacc[2*ntp][1], oacc[2*ntp][2], oacc[2*ntp][3],
                       a0, a1, a2, a3, b0, b1);
                mma16h(oacc[2*ntp+1][0], oacc[2*ntp+1][1], oacc[2*ntp+1][2], oacc[2*ntp+1][3],
                       a0, a1, a2, a3, b2, b3);
            }
        }
    }

    const float inv0 = 1.0f / sumacc[0], inv1 = 1.0f / sumacc[2];
    const int row = q0 + 16 * wid + r;
    #pragma unroll
    for (int nt = 0; nt < 8; nt++) {
        const int col = h * HD + 8 * nt + 2 * c;
        *(__half2*)&g_ctxh[((size_t)(b * Ss + row)) * Hh + col] =
            __floats2half2_rn(oacc[nt][0] * inv0, oacc[nt][1] * inv0);
        *(__half2*)&g_ctxh[((size_t)(b * Ss + row + 8)) * Hh + col] =
            __floats2half2_rn(oacc[nt][2] * inv1, oacc[nt][3] * inv1);
    }
}

// ---------------- launch ------------------------------------------------------
extern "C" void kernel_launch(void* const* d_in, const int* in_sizes, int n_in,
                              void* d_out, int out_size)
{
    const float* x    = (const float*)d_in[0];
    const float* conf = (const float*)d_in[1];
    const float* Wq   = (const float*)d_in[2];
    const float* bq   = (const float*)d_in[3];
    const float* Wk   = (const float*)d_in[4];
    const float* bk   = (const float*)d_in[5];
    const float* Wv   = (const float*)d_in[6];
    const float* bv   = (const float*)d_in[7];
    const float* Weq  = (const float*)d_in[8];
    const float* beq  = (const float*)d_in[9];
    const float* Wek  = (const float*)d_in[10];
    const float* bek  = (const float*)d_in[11];
    const float* Wo   = (const float*)d_in[12];
    const float* bo   = (const float*)d_in[13];
    float* out = (float*)d_out;

    __half *pxh, *pwh;
    cudaGetSymbolAddress((void**)&pxh, g_xh);
    cudaGetSymbolAddress((void**)&pwh, g_whr);

    cudaFuncSetAttribute(gemm_proj, cudaFuncAttributeMaxDynamicSharedMemorySize, GEMMH_SMEM);
    cudaFuncSetAttribute(gemm_out,  cudaFuncAttributeMaxDynamicSharedMemorySize, GEMMH_SMEM);
    cudaFuncSetAttribute(expbias_h, cudaFuncAttributeMaxDynamicSharedMemorySize, EBH_SMEM);
    cudaFuncSetAttribute(attn_h,    cudaFuncAttributeMaxDynamicSharedMemorySize, ATTN_SMEM);

    dim3 blk(256);

    // x + all weights converted in ONE launch (grid sized for the largest slice)
    round_all<<<dim3(Mm * Hh / 4 / 256, 7), blk>>>(x, Wq, Wk, Wv, Wo, Weq, Wek, pxh, pwh);

    gemm_proj<<<dim3(Mm / 128, 28), blk, GEMMH_SMEM>>>(bq, bk, bv, beq, bek);
    expbias_h<<<dim3(Ss / 128, Ss / 128, Bb), blk, EBH_SMEM>>>(conf);
    attn_h<<<dim3(Ss / 128, NH, Bb), blk, ATTN_SMEM>>>();
    gemm_out<<<dim3(Mm / 128, Hh / 128), blk, GEMMH_SMEM>>>(bo, out);
}

// round 16
// speedup vs baseline: 1.1296x; 1.0439x over previous
#include <cuda_runtime.h>
#include <cuda_fp16.h>
#include <math.h>
#include <stdint.h>

#define Bb 4
#define Ss 2048
#define Hh 1024
#define NH 16
#define HD 64
#define Ee 256
#define Mm (Bb*Ss)
#define LOG2E 1.44269504f

// ---------------- static device scratch -------------------------------------
__device__ __half g_qh[(size_t)Mm*Hh];   // fp16 Q (pre-scaled by 0.125*log2e)
__device__ __half g_kh[(size_t)Mm*Hh];
__device__ __half g_vh[(size_t)Mm*Hh];
__device__ __half g_eqh[(size_t)Mm*Ee];
__device__ __half g_ekh[(size_t)Mm*Ee];
__device__ __half g_biash[(size_t)Bb*Ss*Ss];  // bias pre-scaled by log2e
__device__ __half g_ctxh[(size_t)Mm*Hh];
__device__ __half g_xh[(size_t)Mm*Hh];
__device__ __half g_whr[(size_t)4*Hh*Hh + 2*Hh*Ee];

#define OFF_WQ  ((size_t)0)
#define OFF_WK  ((size_t)1*Hh*Hh)
#define OFF_WV  ((size_t)2*Hh*Hh)
#define OFF_WO  ((size_t)3*Hh*Hh)
#define OFF_WEQ ((size_t)4*Hh*Hh)
#define OFF_WEK ((size_t)4*Hh*Hh + (size_t)Hh*Ee)

// ---------------- helpers ----------------------------------------------------
__device__ __forceinline__ void mma16h(float& c0, float& c1, float& c2, float& c3,
                                       unsigned a0, unsigned a1, unsigned a2, unsigned a3,
                                       unsigned b0, unsigned b1) {
    asm volatile("mma.sync.aligned.m16n8k16.row.col.f32.f16.f16.f32 "
                 "{%0,%1,%2,%3},{%4,%5,%6,%7},{%8,%9},{%0,%1,%2,%3};"
                 : "+f"(c0), "+f"(c1), "+f"(c2), "+f"(c3)
                 : "r"(a0), "r"(a1), "r"(a2), "r"(a3), "r"(b0), "r"(b1));
}
__device__ __forceinline__ void mma16hh(unsigned& c0, unsigned& c1,
                                        unsigned a0, unsigned a1, unsigned a2, unsigned a3,
                                        unsigned b0, unsigned b1) {
    asm volatile("mma.sync.aligned.m16n8k16.row.col.f16.f16.f16.f16 "
                 "{%0,%1},{%2,%3,%4,%5},{%6,%7},{%0,%1};"
                 : "+r"(c0), "+r"(c1)
                 : "r"(a0), "r"(a1), "r"(a2), "r"(a3), "r"(b0), "r"(b1));
}
__device__ __forceinline__ void cp16(uint32_t dst, const void* src) {
    asm volatile("cp.async.ca.shared.global [%0], [%1], 16;" :: "r"(dst), "l"(src));
}
__device__ __forceinline__ void ldsm4(unsigned& r0, unsigned& r1, unsigned& r2, unsigned& r3, uint32_t a) {
    asm volatile("ldmatrix.sync.aligned.m8n8.x4.shared.b16 {%0,%1,%2,%3}, [%4];"
                 : "=r"(r0), "=r"(r1), "=r"(r2), "=r"(r3) : "r"(a));
}
__device__ __forceinline__ void ldsm4t(unsigned& r0, unsigned& r1, unsigned& r2, unsigned& r3, uint32_t a) {
    asm volatile("ldmatrix.sync.aligned.m8n8.x4.trans.shared.b16 {%0,%1,%2,%3}, [%4];"
                 : "=r"(r0), "=r"(r1), "=r"(r2), "=r"(r3) : "r"(a));
}
__device__ __forceinline__ unsigned h2ex2(unsigned x) {
    unsigned d; asm("ex2.approx.f16x2 %0, %1;" : "=r"(d) : "r"(x)); return d;
}
#define CP_COMMIT asm volatile("cp.async.commit_group;")
#define CP_WAIT2  asm volatile("cp.async.wait_group 2;")
#define CP_WAIT1  asm volatile("cp.async.wait_group 1;")
#define CP_WAIT0  asm volatile("cp.async.wait_group 0;")

// ---------------- fp32 -> fp16 conversion passes (R13 split) -------------------
__global__ __launch_bounds__(256) void round_h(const float* __restrict__ in,
                                               __half* __restrict__ out, int n4)
{
    int i = blockIdx.x * 256 + threadIdx.x;
    if (i < n4) {
        float4 v = ((const float4*)in)[i];
        __half2* o = (__half2*)out + 2 * (size_t)i;
        o[0] = __floats2half2_rn(v.x, v.y);
        o[1] = __floats2half2_rn(v.z, v.w);
    }
}

__global__ __launch_bounds__(256) void round_w(
    const float* __restrict__ w0, const float* __restrict__ w1,
    const float* __restrict__ w2, const float* __restrict__ w3,
    const float* __restrict__ w4, const float* __restrict__ w5,
    __half* __restrict__ out)
{
    const int z = blockIdx.y;
    const float* src;
    size_t off; int n4;
    switch (z) {
        case 0: src = w0; off = OFF_WQ;  n4 = Hh * Hh / 4; break;
        case 1: src = w1; off = OFF_WK;  n4 = Hh * Hh / 4; break;
        case 2: src = w2; off = OFF_WV;  n4 = Hh * Hh / 4; break;
        case 3: src = w3; off = OFF_WO;  n4 = Hh * Hh / 4; break;
        case 4: src = w4; off = OFF_WEQ; n4 = Hh * Ee / 4; break;
        default: src = w5; off = OFF_WEK; n4 = Hh * Ee / 4; break;
    }
    int i = blockIdx.x * 256 + threadIdx.x;
    if (i < n4) {
        float4 v = ((const float4*)src)[i];
        __half2* o = (__half2*)(out + off) + 2 * (size_t)i;
        o[0] = __floats2half2_rn(v.x, v.y);
        o[1] = __floats2half2_rn(v.z, v.w);
    }
}

// =============================================================================
// fp16 GEMM core (unchanged R13): 4-stage cp.async, fp32 acc
// =============================================================================
#define AS2 40
#define BS2 136
#define A_T2 (128*AS2)
#define B_T2 (32*BS2)
#define G2_STAGE ((A_T2 + B_T2)*2)
#define GEMMH_SMEM (4*G2_STAGE)

__device__ __forceinline__ void g_load(uint32_t sbase, const __half* A, const __half* W,
                                       int N, int K, int m0, int n0, int s, int tid)
{
    const uint32_t st = sbase + (uint32_t)((s & 3) * G2_STAGE);
    const int kt = s * 32;
    #pragma unroll
    for (int i = 0; i < 2; i++) {
        int lin = tid + i * 256, row = lin >> 2, ch = (lin & 3) * 8;
        cp16(st + (uint32_t)(row * AS2 + ch) * 2, A + (size_t)(m0 + row) * K + kt + ch);
    }
    #pragma unroll
    for (int i = 0; i < 2; i++) {
        int lin = tid + i * 256, row = lin >> 4, ch = (lin & 15) * 8;
        cp16(st + (uint32_t)(A_T2 + row * BS2 + ch) * 2, W + (size_t)(kt + row) * N + n0 + ch);
    }
}

__device__ __forceinline__ void gemmh_body(
    const __half* __restrict__ A, const __half* __restrict__ W,
    const float* __restrict__ bias, float* __restrict__ Cf, __half* __restrict__ Ch,
    int N, int K, int mode, float oscale, int m0, int n0, char* smc)
{
    const int tid = threadIdx.x, lane = tid & 31, wid = tid >> 5;
    const int wm = wid >> 2, wn = wid & 3;
    const int r = lane >> 2, c = lane & 3;
    const uint32_t sbase = (uint32_t)__cvta_generic_to_shared(smc);

    float acc[4][4][4];
    #pragma unroll
    for (int i = 0; i < 4; i++)
        #pragma unroll
        for (int j = 0; j < 4; j++)
            #pragma unroll
            for (int q = 0; q < 4; q++) acc[i][j][q] = 0.f;

    const uint32_t aLane = (uint32_t)((lane & 15) * (AS2 * 2) + (lane >> 4) * 16);
    const uint32_t bLane = (uint32_t)((lane & 15) * (BS2 * 2) + (lane >> 4) * 16);

    const int niter = K / 32;
    #pragma unroll
    for (int s = 0; s < 3; s++) { g_load(sbase, A, W, N, K, m0, n0, s, tid); CP_COMMIT; }

    for (int it = 0; it < niter; it++) {
        if (it + 2 < niter) { CP_WAIT2; }
        else if (it + 1 < niter) { CP_WAIT1; }
        else { CP_WAIT0; }
        __syncthreads();

        if (it + 3 < niter) { g_load(sbase, A, W, N, K, m0, n0, it + 3, tid); CP_COMMIT; }

        const uint32_t stA = sbase + (uint32_t)((it & 3) * G2_STAGE);
        const uint32_t stB = stA + A_T2 * 2;
        #pragma unroll
        for (int kc = 0; kc < 2; kc++) {
            unsigned af[4][4];
            #pragma unroll
            for (int mt = 0; mt < 4; mt++)
                ldsm4(af[mt][0], af[mt][1], af[mt][2], af[mt][3],
                      stA + (uint32_t)((64 * wm + 16 * mt) * (AS2 * 2) + kc * 32) + aLane);
            unsigned bf[2][4];
            #pragma unroll
            for (int ntp = 0; ntp < 2; ntp++)
                ldsm4t(bf[ntp][0], bf[ntp][1], bf[ntp][2], bf[ntp][3],
                       stB + (uint32_t)(kc * 16 * (BS2 * 2) + (32 * wn + ntp * 16) * 2) + bLane);
            #pragma unroll
            for (int mt = 0; mt < 4; mt++)
                #pragma unroll
                for (int ntp = 0; ntp < 2; ntp++) {
                    mma16h(acc[mt][2*ntp][0], acc[mt][2*ntp][1], acc[mt][2*ntp][2], acc[mt][2*ntp][3],
                           af[mt][0], af[mt][1], af[mt][2], af[mt][3], bf[ntp][0], bf[ntp][1]);
                    mma16h(acc[mt][2*ntp+1][0], acc[mt][2*ntp+1][1], acc[mt][2*ntp+1][2], acc[mt][2*ntp+1][3],
                           af[mt][0], af[mt][1], af[mt][2], af[mt][3], bf[ntp][2], bf[ntp][3]);
                }
        }
    }

    #pragma unroll
    for (int mt = 0; mt < 4; mt++) {
        const int row = m0 + 64 * wm + 16 * mt + r;
        #pragma unroll
        for (int nt = 0; nt < 4; nt++) {
            const int col = n0 + 32 * wn + 8 * nt + 2 * c;
            float2 bz = *(const float2*)(bias + col);
            float2 o0 = { acc[mt][nt][0] + bz.x, acc[mt][nt][1] + bz.y };
            float2 o1 = { acc[mt][nt][2] + bz.x, acc[mt][nt][3] + bz.y };
            if (mode == 2) {
                *(__half2*)&Ch[(size_t)row * N + col] = __floats2half2_rn(o0.x * oscale, o0.y * oscale);
                *(__half2*)&Ch[(size_t)(row + 8) * N + col] = __floats2half2_rn(o1.x * oscale, o1.y * oscale);
            } else {
                *(float2*)&Cf[(size_t)row * N + col] = o0;
                *(float2*)&Cf[(size_t)(row + 8) * N + col] = o1;
            }
        }
    }
}

__global__ __launch_bounds__(256, 2) void gemm_proj(
    const float* __restrict__ bq, const float* __restrict__ bk, const float* __restrict__ bv,
    const float* __restrict__ beq, const float* __restrict__ bek)
{
    extern __shared__ char smc[];
    const int y = blockIdx.y;
    const int m0 = blockIdx.x * 128;
    if (y < 24) {
        const int z = y >> 3, ny = y & 7;
        const __half* W = g_whr + (z == 0 ? OFF_WQ : (z == 1 ? OFF_WK : OFF_WV));
        const float* bias = z == 0 ? bq : (z == 1 ? bk : bv);
        __half* Ch = z == 0 ? g_qh : (z == 1 ? g_kh : g_vh);
        const float sc = z == 0 ? 0.125f * LOG2E : 1.0f;
        gemmh_body(g_xh, W, bias, 0, Ch, Hh, Hh, 2, sc, m0, ny * 128, smc);
    } else {
        const int idx = y - 24, z = idx >> 1, ny = idx & 1;
        const __half* W = g_whr + (z == 0 ? OFF_WEQ : OFF_WEK);
        const float* bias = z == 0 ? beq : bek;
        __half* Ch = z == 0 ? g_eqh : g_ekh;
        gemmh_body(g_xh, W, bias, 0, Ch, Ee, Hh, 2, 1.f, m0, ny * 128, smc);
    }
}

__global__ __launch_bounds__(256, 2) void gemm_out(
    const float* __restrict__ bias, float* __restrict__ C)
{
    extern __shared__ char smc[];
    gemmh_body(g_ctxh, g_whr + OFF_WO, bias, C, 0, Hh, Hh, 0, 1.f,
               blockIdx.x * 128, blockIdx.y * 128, smc);
}

// =============================================================================
// exp-bias GEMM (unchanged R13)
// =============================================================================
#define EB2_STAGE (2*A_T2*2)
#define EBH_SMEM (4*EB2_STAGE)

__device__ __forceinline__ void eb_load(uint32_t sbase, const __half* A, const __half* Bm,
                                        int m0, int n0, int s, int tid)
{
    const uint32_t st = sbase + (uint32_t)((s & 3) * EB2_STAGE);
    const int kt = s * 32;
    #pragma unroll
    for (int i = 0; i < 2; i++) {
        int lin = tid + i * 256, row = lin >> 2, ch = (lin & 3) * 8;
        cp16(st + (uint32_t)(row * AS2 + ch) * 2, A + (size_t)(m0 + row) * Ee + kt + ch);
        cp16(st + (uint32_t)(A_T2 + row * AS2 + ch) * 2, Bm + (size_t)(n0 + row) * Ee + kt + ch);
    }
}

__global__ __launch_bounds__(256, 2) void expbias_h(const float* __restrict__ conf)
{
    extern __shared__ char smc[];
    const int b = blockIdx.z;
    const __half* A  = g_eqh + (size_t)b * Ss * Ee;
    const __half* Bm = g_ekh + (size_t)b * Ss * Ee;
    __half* C = g_biash + (size_t)b * Ss * Ss;
    const float scale = 0.3f * __ldg(&conf[b]) * (1.0f / 16.0f) * LOG2E;

    const int tid = threadIdx.x, lane = tid & 31, wid = tid >> 5;
    const int wm = wid >> 2, wn = wid & 3;
    const int r = lane >> 2, c = lane & 3;
    const int m0 = blockIdx.x * 128, n0 = blockIdx.y * 128;
    const uint32_t sbase = (uint32_t)__cvta_generic_to_shared(smc);

    float acc[4][4][4];
    #pragma unroll
    for (int i = 0; i < 4; i++)
        #pragma unroll
        for (int j = 0; j < 4; j++)
            #pragma unroll
            for (int q = 0; q < 4; q++) acc[i][j][q] = 0.f;

    const uint32_t aLane = (uint32_t)((lane & 15) * (AS2 * 2) + (lane >> 4) * 16);
    const uint32_t bLaneE = (uint32_t)((((lane >> 4) * 8 + (lane & 7)) * AS2) * 2 + ((lane >> 3) & 1) * 16);

    const int niter = Ee / 32;
    #pragma unroll
    for (int s = 0; s < 3; s++) { eb_load(sbase, A, Bm, m0, n0, s, tid); CP_COMMIT; }

    for (int it = 0; it < niter; it++) {
        if (it + 2 < niter) { CP_WAIT2; }
        else if (it + 1 < niter) { CP_WAIT1; }
        else { CP_WAIT0; }
        __syncthreads();

        if (it + 3 < niter) { eb_load(sbase, A, Bm, m0, n0, it + 3, tid); CP_COMMIT; }

        const uint32_t stA = sbase + (uint32_t)((it & 3) * EB2_STAGE);
        const uint32_t stB = stA + A_T2 * 2;
        #pragma unroll
        for (int kc = 0; kc < 2; kc++) {
            unsigned af[4][4];
            #pragma unroll
            for (int mt = 0; mt < 4; mt++)
                ldsm4(af[mt][0], af[mt][1], af[mt][2], af[mt][3],
                      stA + (uint32_t)((64 * wm + 16 * mt) * (AS2 * 2) + kc * 32) + aLane);
            unsigned bf[2][4];
            #pragma unroll
            for (int ntp = 0; ntp < 2; ntp++)
                ldsm4(bf[ntp][0], bf[ntp][1], bf[ntp][2], bf[ntp][3],
                      stB + (uint32_t)((32 * wn + ntp * 16) * (AS2 * 2) + kc * 32) + bLaneE);
            #pragma unroll
            for (int mt = 0; mt < 4; mt++)
                #pragma unroll
                for (int ntp = 0; ntp < 2; ntp++) {
                    mma16h(acc[mt][2*ntp][0], acc[mt][2*ntp][1], acc[mt][2*ntp][2], acc[mt][2*ntp][3],
                           af[mt][0], af[mt][1], af[mt][2], af[mt][3], bf[ntp][0], bf[ntp][1]);
                    mma16h(acc[mt][2*ntp+1][0], acc[mt][2*ntp+1][1], acc[mt][2*ntp+1][2], acc[mt][2*ntp+1][3],
                           af[mt][0], af[mt][1], af[mt][2], af[mt][3], bf[ntp][2], bf[ntp][3]);
                }
        }
    }

    #pragma unroll
    for (int mt = 0; mt < 4; mt++) {
        const int row = m0 + 64 * wm + 16 * mt + r;
        #pragma unroll
        for (int nt = 0; nt < 4; nt++) {
            const int col = n0 + 32 * wn + 8 * nt + 2 * c;
            *(__half2*)&C[(size_t)row * Ss + col] =
                __floats2half2_rn(acc[mt][nt][0] * scale, acc[mt][nt][1] * scale);
            *(__half2*)&C[(size_t)(row + 8) * Ss + col] =
                __floats2half2_rn(acc[mt][nt][2] * scale, acc[mt][nt][3] * scale);
        }
    }
}

// =============================================================================
// fp16 flash attention: 256 q-rows/CTA, warp owns 32 q-rows (2 m-tiles) x 64
// keys -> each K/V ldsm fragment feeds 2x MMAs (halves L1 traffic per MMA).
// f16-acc QK, ex2 on acc frags, ones-MMA row sums, fp32-acc PV. 1 CTA/SM.
// =============================================================================
#define KSh 72
#define BSh 72
#define V_OFFB (64*KSh*2)
#define B_OFFB (2*64*KSh*2)
#define STAGE_B (2*64*KSh*2 + 256*BSh*2)   // 55296 B
#define ATTN_SMEM (2*STAGE_B)               // 110592 B
#define ONES2 0x3C003C00u

__global__ __launch_bounds__(256, 1) void attn_h()
{
    extern __shared__ char smc[];
    const int tid = threadIdx.x, lane = tid & 31, wid = tid >> 5;
    const int r = lane >> 2, c = lane & 3;
    const int q0 = blockIdx.x * 256, h = blockIdx.y, b = blockIdx.z;
    const uint32_t sbase = (uint32_t)__cvta_generic_to_shared(smc);

    // ---- stage Q [256x64] into stage-0 area (36864 B < 55296) ----
    const __half* gq = g_qh + ((size_t)(b * Ss + q0)) * Hh + h * HD;
    #pragma unroll
    for (int i = 0; i < 8; i++) {
        int lin = tid + i * 256, row = lin >> 3, ch = (lin & 7) * 8;
        cp16(sbase + (uint32_t)(row * KSh + ch) * 2, gq + (size_t)row * Hh + ch);
    }
    CP_COMMIT; CP_WAIT0;
    __syncthreads();

    unsigned qf[2][4][4];
    {
        const __half* Qs = (const __half*)smc;
        #pragma unroll
        for (int mt = 0; mt < 2; mt++)
            #pragma unroll
            for (int kc = 0; kc < 4; kc++) {
                const int idx = (32 * wid + 16 * mt + r) * KSh + kc * 16 + 2 * c;
                qf[mt][kc][0] = *(const unsigned*)&Qs[idx];
                qf[mt][kc][1] = *(const unsigned*)&Qs[idx + 8 * KSh];
                qf[mt][kc][2] = *(const unsigned*)&Qs[idx + 8];
                qf[mt][kc][3] = *(const unsigned*)&Qs[idx + 8 * KSh + 8];
            }
    }
    __syncthreads();

    const __half* bias_base = g_biash + ((size_t)b * Ss + q0) * Ss;
    const size_t kv_base = (size_t)(b * Ss) * Hh + h * HD;

    // ---- prefetch tile 0 ----
    {
        const uint32_t st = sbase;
        #pragma unroll
        for (int i = 0; i < 2; i++) {
            int lin = tid + i * 256, row = lin >> 3, ch = (lin & 7) * 8;
            size_t go = kv_base + (size_t)row * Hh + ch;
            cp16(st + (uint32_t)(row * KSh + ch) * 2, g_kh + go);
            cp16(st + V_OFFB + (uint32_t)(row * KSh + ch) * 2, g_vh + go);
        }
        #pragma unroll
        for (int i = 0; i < 8; i++) {
            int lin = tid + i * 256, row = lin >> 3, ch = (lin & 7) * 8;
            cp16(st + B_OFFB + (uint32_t)(row * BSh + ch) * 2, bias_base + (size_t)row * Ss + ch);
        }
        CP_COMMIT;
    }

    float oacc[2][8][4];
    #pragma unroll
    for (int mt = 0; mt < 2; mt++)
        #pragma unroll
        for (int i = 0; i < 8; i++)
            #pragma unroll
            for (int j = 0; j < 4; j++) oacc[mt][i][j] = 0.f;
    float sumacc[2][4] = {{0.f,0.f,0.f,0.f},{0.f,0.f,0.f,0.f}};

    const uint32_t klane4 = (uint32_t)((((lane >> 4) * 8 + (lane & 7)) * KSh) * 2 + ((lane >> 3) & 1) * 16);
    const uint32_t vlane4 = (uint32_t)(((lane & 15) * KSh) * 2 + (lane >> 4) * 16);

    const int NT = Ss / 64;
    for (int kt = 0; kt < NT; kt++) {
        CP_WAIT0;
        __syncthreads();

        if (kt + 1 < NT) {
            const int k1 = (kt + 1) * 64;
            const uint32_t st = sbase + (uint32_t)(((kt + 1) & 1) * STAGE_B);
            #pragma unroll
            for (int i = 0; i < 2; i++) {
                int lin = tid + i * 256, row = lin >> 3, ch = (lin & 7) * 8;
                size_t go = kv_base + (size_t)(k1 + row) * Hh + ch;
                cp16(st + (uint32_t)(row * KSh + ch) * 2, g_kh + go);
                cp16(st + V_OFFB + (uint32_t)(row * KSh + ch) * 2, g_vh + go);
            }
            #pragma unroll
            for (int i = 0; i < 8; i++) {
                int lin = tid + i * 256, row = lin >> 3, ch = (lin & 7) * 8;
                cp16(st + B_OFFB + (uint32_t)(row * BSh + ch) * 2,
                     bias_base + (size_t)row * Ss + k1 + ch);
            }
            CP_COMMIT;
        }

        const uint32_t stage = sbase + (uint32_t)((kt & 1) * STAGE_B);
        const uint32_t kBase = stage + klane4;
        const uint32_t vBase = stage + V_OFFB + vlane4;
        const __half* Bs_ = (const __half*)(smc + (kt & 1) * STAGE_B + B_OFFB);

        // init f16x2 score accumulators directly from fp16 bias
        unsigned sacc[2][8][2];
        #pragma unroll
        for (int mt = 0; mt < 2; mt++)
            #pragma unroll
            for (int nt = 0; nt < 8; nt++) {
                sacc[mt][nt][0] = *(const unsigned*)&Bs_[(32 * wid + 16 * mt + r) * BSh + 8 * nt + 2 * c];
                sacc[mt][nt][1] = *(const unsigned*)&Bs_[(32 * wid + 16 * mt + r + 8) * BSh + 8 * nt + 2 * c];
            }

        // QK: each K fragment load feeds both m-tiles
        #pragma unroll
        for (int kc = 0; kc < 4; kc++) {
            #pragma unroll
            for (int ntp = 0; ntp < 4; ntp++) {
                unsigned b0, b1, b2, b3;
                ldsm4(b0, b1, b2, b3, kBase + (uint32_t)(ntp * (16 * KSh * 2) + kc * 32));
                #pragma unroll
                for (int mt = 0; mt < 2; mt++) {
                    mma16hh(sacc[mt][2*ntp][0], sacc[mt][2*ntp][1],
                            qf[mt][kc][0], qf[mt][kc][1], qf[mt][kc][2], qf[mt][kc][3], b0, b1);
                    mma16hh(sacc[mt][2*ntp+1][0], sacc[mt][2*ntp+1][1],
                            qf[mt][kc][0], qf[mt][kc][1], qf[mt][kc][2], qf[mt][kc][3], b2, b3);
                }
            }
        }

        // p = 2^s on acc frags; row sums; PV (V frags shared across m-tiles)
        #pragma unroll
        for (int j = 0; j < 4; j++) {
            unsigned a[2][4];
            #pragma unroll
            for (int mt = 0; mt < 2; mt++) {
                a[mt][0] = h2ex2(sacc[mt][2*j][0]);
                a[mt][1] = h2ex2(sacc[mt][2*j][1]);
                a[mt][2] = h2ex2(sacc[mt][2*j+1][0]);
                a[mt][3] = h2ex2(sacc[mt][2*j+1][1]);
                mma16h(sumacc[mt][0], sumacc[mt][1], sumacc[mt][2], sumacc[mt][3],
                       a[mt][0], a[mt][1], a[mt][2], a[mt][3], ONES2, ONES2);
            }
            #pragma unroll
            for (int ntp = 0; ntp < 4; ntp++) {
                unsigned b0, b1, b2, b3;
                ldsm4t(b0, b1, b2, b3, vBase + (uint32_t)(j * (16 * KSh * 2) + ntp * 32));
                #pragma unroll
                for (int mt = 0; mt < 2; mt++) {
                    mma16h(oacc[mt][2*ntp][0], oacc[mt][2*ntp][1], oacc[mt][2*ntp][2], oacc[mt][2*ntp][3],
                           a[mt][0], a[mt][1], a[mt][2], a[mt][3], b0, b1);
                    mma16h(oacc[mt][2*ntp+1][0], oacc[mt][2*ntp+1][1], oacc[mt][2*ntp+1][2], oacc[mt][2*ntp+1][3],
                           a[mt][0], a[mt][1], a[mt][2], a[mt][3], b2, b3);
                }
            }
        }
    }

    #pragma unroll
    for (int mt = 0; mt < 2; mt++) {
        const float inv0 = 1.0f / sumacc[mt][0], inv1 = 1.0f / sumacc[mt][2];
        const int row = q0 + 32 * wid + 16 * mt + r;
        #pragma unroll
        for (int nt = 0; nt < 8; nt++) {
            const int col = h * HD + 8 * nt + 2 * c;
            *(__half2*)&g_ctxh[((size_t)(b * Ss + row)) * Hh + col] =
                __floats2half2_rn(oacc[mt][nt][0] * inv0, oacc[mt][nt][1] * inv0);
            *(__half2*)&g_ctxh[((size_t)(b * Ss + row + 8)) * Hh + col] =
                __floats2half2_rn(oacc[mt][nt][2] * inv1, oacc[mt][nt][3] * inv1);
        }
    }
}

// ---------------- launch ------------------------------------------------------
extern "C" void kernel_launch(void* const* d_in, const int* in_sizes, int n_in,
                              void* d_out, int out_size)
{
    const float* x    = (const float*)d_in[0];
    const float* conf = (const float*)d_in[1];
    const float* Wq   = (const float*)d_in[2];
    const float* bq   = (const float*)d_in[3];
    const float* Wk   = (const float*)d_in[4];
    const float* bk   = (const float*)d_in[5];
    const float* Wv   = (const float*)d_in[6];
    const float* bv   = (const float*)d_in[7];
    const float* Weq  = (const float*)d_in[8];
    const float* beq  = (const float*)d_in[9];
    const float* Wek  = (const float*)d_in[10];
    const float* bek  = (const float*)d_in[11];
    const float* Wo   = (const float*)d_in[12];
    const float* bo   = (const float*)d_in[13];
    float* out = (float*)d_out;

    __half *pxh, *pwh;
    cudaGetSymbolAddress((void**)&pxh, g_xh);
    cudaGetSymbolAddress((void**)&pwh, g_whr);

    cudaFuncSetAttribute(gemm_proj, cudaFuncAttributeMaxDynamicSharedMemorySize, GEMMH_SMEM);
    cudaFuncSetAttribute(gemm_out,  cudaFuncAttributeMaxDynamicSharedMemorySize, GEMMH_SMEM);
    cudaFuncSetAttribute(expbias_h, cudaFuncAttributeMaxDynamicSharedMemorySize, EBH_SMEM);
    cudaFuncSetAttribute(attn_h,    cudaFuncAttributeMaxDynamicSharedMemorySize, ATTN_SMEM);

    dim3 blk(256);

    round_h<<<(Mm * Hh / 4 + 255) / 256, blk>>>(x, pxh, Mm * Hh / 4);
    round_w<<<dim3(Hh * Hh / 4 / 256, 6), blk>>>(Wq, Wk, Wv, Wo, Weq, Wek, pwh);

    gemm_proj<<<dim3(Mm / 128, 28), blk, GEMMH_SMEM>>>(bq, bk, bv, beq, bek);
    expbias_h<<<dim3(Ss / 128, Ss / 128, Bb), blk, EBH_SMEM>>>(conf);
    attn_h<<<dim3(Ss / 256, NH, Bb), blk, ATTN_SMEM>>>();
    gemm_out<<<dim3(Mm / 128, Hh / 128), blk, GEMMH_SMEM>>>(bo, out);
}